// round 15
// baseline (speedup 1.0000x reference)
#include <cuda_runtime.h>
#include <cuda_fp16.h>
#include <math.h>
#include <stdint.h>

// ---------------------------------------------------------------------------
// Problem constants
// ---------------------------------------------------------------------------
#define Bc    8
#define Sc    2048
#define DMc   1024
#define DKc   512
#define DVc   512
#define DOUTc 1024
#define NTc   (Bc * Sc)              // 16384 tokens

static const long OFF_OUT = 0L;
static const long OFF_RES = (long)NTc * DOUTc;                   // 16777216
static const long OFF_ATT = OFF_RES + (long)NTc * DKc;           // 25165824

#define INV_TEMP 0.04419417382415922f   // 1/sqrt(512)

// ---------------------------------------------------------------------------
// Scratch (static device globals — no allocation at runtime)
// fp32: GEMM outputs feeding LN + residual.  fp16: all GEMM operands.
// ---------------------------------------------------------------------------
__device__ __align__(16) float  g_qp [(size_t)NTc * DKc];
__device__ __align__(16) float  g_kp [(size_t)NTc * DKc];
__device__ __align__(16) float  g_vp [(size_t)NTc * DVc];
__device__ __align__(16) __half g_qh [(size_t)NTc * DMc];   // fp16(q)
__device__ __align__(16) __half g_kh [(size_t)NTc * DMc];
__device__ __align__(16) __half g_vh [(size_t)NTc * DMc];
__device__ __align__(16) __half g_qn [(size_t)NTc * DKc];   // LN(q); later t1h
__device__ __align__(16) __half g_kn [(size_t)NTc * DKc];   // LN(k); later t2h
__device__ __align__(16) __half g_vn [(size_t)NTc * DVc];   // LN(v)
__device__ __align__(16) __half g_vpT[(size_t)DVc * NTc];   // LN(v)^T
__device__ __align__(16) __half g_ath[(size_t)NTc * Sc];    // fp16(attn)
__device__ __align__(16) __half g_wqT[(size_t)DKc * DMc];
__device__ __align__(16) __half g_wkT[(size_t)DKc * DMc];
__device__ __align__(16) __half g_wvT[(size_t)DVc * DMc];
__device__ __align__(16) __half g_w1T[(size_t)DVc * DVc];
__device__ __align__(16) __half g_w2T[(size_t)DOUTc * DVc];

// ---------------------------------------------------------------------------
// helpers
// ---------------------------------------------------------------------------
__device__ __forceinline__ uint32_t f2tf32(float f) {
    uint32_t r;
    asm("cvt.rna.tf32.f32 %0, %1;" : "=r"(r) : "f"(f));
    return r;
}
__device__ __forceinline__ float roundtf(float f) { return __uint_as_float(f2tf32(f)); }

__device__ __forceinline__ uint32_t smem_u32(const void* p) {
    uint32_t a;
    asm("{ .reg .u64 t; cvta.to.shared.u64 t, %1; cvt.u32.u64 %0, t; }" : "=r"(a) : "l"(p));
    return a;
}
__device__ __forceinline__ void cp_async16(uint32_t dst, const void* src) {
    asm volatile("cp.async.cg.shared.global [%0], [%1], 16;" :: "r"(dst), "l"(src));
}
#define CP_COMMIT() asm volatile("cp.async.commit_group;" ::: "memory")
#define CP_WAIT2()  asm volatile("cp.async.wait_group 2;" ::: "memory")

__device__ __forceinline__ void ldsm_x4(uint32_t* r, uint32_t addr) {
    asm volatile("ldmatrix.sync.aligned.m8n8.x4.shared.b16 {%0,%1,%2,%3}, [%4];"
                 : "=r"(r[0]), "=r"(r[1]), "=r"(r[2]), "=r"(r[3]) : "r"(addr));
}
// fp16 mma, fp32 accumulate: D[16,8] += A[16,16] * B[16,8] (B col-major = [n][k])
__device__ __forceinline__ void mma_16x8x16(float* c, const uint32_t* a, const uint32_t* b) {
    asm volatile(
        "mma.sync.aligned.m16n8k16.row.col.f32.f16.f16.f32 "
        "{%0,%1,%2,%3}, {%4,%5,%6,%7}, {%8,%9}, {%0,%1,%2,%3};"
        : "+f"(c[0]), "+f"(c[1]), "+f"(c[2]), "+f"(c[3])
        : "r"(a[0]), "r"(a[1]), "r"(a[2]), "r"(a[3]), "r"(b[0]), "r"(b[1]));
}

// ---------------------------------------------------------------------------
// fp16 GEMM: C[M,N] = alpha * A[M,K] @ Bt[N,K]^T (+bias) (+relu)
// A, Bt fp16; C fp32 (OUT_HALF=0) or fp16 (OUT_HALF=1). fp32 accumulate.
// BM=BN=128, BK=32, 128 threads (4 warps, 64x64 warp tiles), 4-stage cp.async
// (wait_group 2 => 3-stage lookahead). Smem rows: 32 halfs + 8 pad = stride 40
// halfs (80B); 8 consecutive rows hit word offsets {0,20,8,28,16,4,24,12} ->
// every ldmatrix phase and cp.async fill spans all 32 banks, conflict-free.
// Fragment rule (validated R12-R14): ldmatrix lane l -> row l>>2, word l&3.
// ---------------------------------------------------------------------------
#define STRIDE_H 40
#define TILE_BYTES_H (128 * STRIDE_H * 2)     // 10240
#define NSTAGE 4
#define SMEM_DYN (NSTAGE * 2 * TILE_BYTES_H)  // 81920

#define BM 128
#define BN 128
#define BK 32

template<bool BIAS, bool RELU, bool OUT_HALF>
__global__ __launch_bounds__(128, 2)
void mma_gemm(const __half* __restrict__ A, const __half* __restrict__ Bt,
              const float* __restrict__ bias, void* __restrict__ Cv,
              int M, int N, int K, int ldB,
              long sA, long sB, long sC, float alpha)
{
    extern __shared__ __align__(16) __half smem[];

    A  += (long)blockIdx.z * sA;
    Bt += (long)blockIdx.z * sB;

    const int tid  = threadIdx.x;
    const int wid  = tid >> 5;
    const int lane = tid & 31;
    const int g    = lane >> 2;
    const int tg   = lane & 3;
    const int wm   = (wid & 1);
    const int wn   = (wid >> 1);
    const int m0   = blockIdx.y * BM;
    const int n0   = blockIdx.x * BN;

    const uint32_t sAu = smem_u32(smem);
    const uint32_t sBu = sAu + NSTAGE * TILE_BYTES_H;

    // loader: 512 chunks (128 rows x 4 k-octs of 8 halfs) per tile, 4/thread
    int rowc[4];
#pragma unroll
    for (int i = 0; i < 4; i++) rowc[i] = (i * 128 + tid) >> 2;
    const int koct = (tid & 3) * 8;               // half offset (0,8,16,24)

    // ldmatrix bases (bytes). grp = lane>>3.
    const int grp = lane >> 3;
    const uint32_t aAddr0 = sAu + (uint32_t)((((wm * 64 + (grp & 1) * 8 + (lane & 7)) * STRIDE_H)
                                              + (grp >> 1) * 8) * 2);
    const uint32_t bAddr0 = sBu + (uint32_t)((((wn * 64 + (grp >> 1) * 8 + (lane & 7)) * STRIDE_H)
                                              + (grp & 1) * 8) * 2);

    float acc[4][8][4];
#pragma unroll
    for (int i = 0; i < 4; i++)
#pragma unroll
        for (int j = 0; j < 8; j++)
#pragma unroll
            for (int r = 0; r < 4; r++) acc[i][j][r] = 0.f;

    const int T = K / BK;

    // ---- prologue: stages 0..2
#pragma unroll
    for (int s = 0; s < 3; s++) {
        if (s < T) {
            const int kc = s * BK;
            const uint32_t so = (uint32_t)(s * TILE_BYTES_H);
#pragma unroll
            for (int i = 0; i < 4; i++) {
                uint32_t d = so + (uint32_t)((rowc[i] * STRIDE_H + koct) * 2);
                cp_async16(sAu + d, A  + (long)(m0 + rowc[i]) * K   + kc + koct);
                cp_async16(sBu + d, Bt + (long)(n0 + rowc[i]) * ldB + kc + koct);
            }
        }
        CP_COMMIT();
    }

    int cur = 0;
    for (int it = 0; it < T; it++) {
        CP_WAIT2();        // stage `it` complete (<=2 groups pending)
        __syncthreads();   // all warps done with the buffer we are about to refill

        if (it + 3 < T) {
            int ib = cur + 3; if (ib >= NSTAGE) ib -= NSTAGE;
            const int kc = (it + 3) * BK;
            const uint32_t so = (uint32_t)(ib * TILE_BYTES_H);
#pragma unroll
            for (int i = 0; i < 4; i++) {
                uint32_t d = so + (uint32_t)((rowc[i] * STRIDE_H + koct) * 2);
                cp_async16(sAu + d, A  + (long)(m0 + rowc[i]) * K   + kc + koct);
                cp_async16(sBu + d, Bt + (long)(n0 + rowc[i]) * ldB + kc + koct);
            }
        }
        CP_COMMIT();

        // ---- compute buffer cur: 2 k16-steps
        const uint32_t bufOff = (uint32_t)(cur * TILE_BYTES_H);
#pragma unroll
        for (int kt = 0; kt < 2; kt++) {
            const uint32_t kOff = bufOff + kt * 32;   // 16 halfs = 32B
            uint32_t a[4][4];
#pragma unroll
            for (int mi = 0; mi < 4; mi++)
                ldsm_x4(a[mi], aAddr0 + kOff + mi * (16 * STRIDE_H * 2));
            uint32_t b[4][4];   // [p] covers n-atoms 2p,2p+1: {b0,b1,b0',b1'}
#pragma unroll
            for (int p = 0; p < 4; p++)
                ldsm_x4(b[p], bAddr0 + kOff + p * (16 * STRIDE_H * 2));
#pragma unroll
            for (int mi = 0; mi < 4; mi++)
#pragma unroll
                for (int ni = 0; ni < 8; ni++)
                    mma_16x8x16(acc[mi][ni], a[mi], &b[ni >> 1][(ni & 1) * 2]);
        }

        if (++cur == NSTAGE) cur = 0;
    }

    // ---- epilogue
#pragma unroll
    for (int mi = 0; mi < 4; mi++) {
#pragma unroll
        for (int half = 0; half < 2; half++) {
            const long row = m0 + wm * 64 + mi * 16 + g + half * 8;
#pragma unroll
            for (int ni = 0; ni < 8; ni++) {
                const int col = n0 + wn * 64 + ni * 8 + 2 * tg;
                float rx = acc[mi][ni][half * 2 + 0] * alpha;
                float ry = acc[mi][ni][half * 2 + 1] * alpha;
                if (BIAS) {
                    float2 b2v = *reinterpret_cast<const float2*>(bias + col);
                    rx += b2v.x; ry += b2v.y;
                }
                if (RELU) { rx = fmaxf(rx, 0.f); ry = fmaxf(ry, 0.f); }
                if (OUT_HALF) {
                    __half* C16 = (__half*)Cv + (long)blockIdx.z * sC;
                    *reinterpret_cast<__half2*>(C16 + row * (long)N + col) =
                        __floats2half2_rn(rx, ry);
                } else {
                    float* C = (float*)Cv + (long)blockIdx.z * sC;
                    float2 r; r.x = rx; r.y = ry;
                    *reinterpret_cast<float2*>(C + row * (long)N + col) = r;
                }
            }
        }
    }
}

// ---------------------------------------------------------------------------
// fp32 -> fp16 elementwise convert (8 per thread)
// ---------------------------------------------------------------------------
__global__ __launch_bounds__(256)
void cvt_f2h(const float* __restrict__ in, __half* __restrict__ out, long n)
{
    long i = ((long)blockIdx.x * 256 + threadIdx.x) * 8;
    if (i >= n) return;
    float4 a = *reinterpret_cast<const float4*>(in + i);
    float4 b = *reinterpret_cast<const float4*>(in + i + 4);
    __half2* o = reinterpret_cast<__half2*>(out + i);
    o[0] = __floats2half2_rn(a.x, a.y);
    o[1] = __floats2half2_rn(a.z, a.w);
    o[2] = __floats2half2_rn(b.x, b.y);
    o[3] = __floats2half2_rn(b.z, b.w);
}

// ---------------------------------------------------------------------------
// 32x32 transposes: fp32 in -> fp16 out (weights), fp16 in -> fp16 out (vn)
// ---------------------------------------------------------------------------
__global__ __launch_bounds__(256)
void transpose_f2h(const float* __restrict__ in, __half* __restrict__ out, int R, int C)
{
    __shared__ float t[32][33];
    int c0 = blockIdx.x * 32, r0 = blockIdx.y * 32;
#pragma unroll
    for (int i = 0; i < 32; i += 8)
        t[threadIdx.y + i][threadIdx.x] = in[(long)(r0 + threadIdx.y + i) * C + c0 + threadIdx.x];
    __syncthreads();
#pragma unroll
    for (int i = 0; i < 32; i += 8)
        out[(long)(c0 + threadIdx.y + i) * R + r0 + threadIdx.x] =
            __float2half_rn(t[threadIdx.x][threadIdx.y + i]);
}

__global__ __launch_bounds__(256)
void transpose_h2h(const __half* __restrict__ in, __half* __restrict__ out, int R, int C)
{
    __shared__ float t[32][33];
    int c0 = blockIdx.x * 32, r0 = blockIdx.y * 32;
#pragma unroll
    for (int i = 0; i < 32; i += 8)
        t[threadIdx.y + i][threadIdx.x] =
            __half2float(in[(long)(r0 + threadIdx.y + i) * C + c0 + threadIdx.x]);
    __syncthreads();
#pragma unroll
    for (int i = 0; i < 32; i += 8)
        out[(long)(c0 + threadIdx.y + i) * R + r0 + threadIdx.x] =
            __float2half_rn(t[threadIdx.x][threadIdx.y + i]);
}

// ---------------------------------------------------------------------------
// LayerNorm D=512: fp32 in -> fp16 normalized out (+ optional raw fp32 residual)
// ---------------------------------------------------------------------------
__global__ __launch_bounds__(128)
void ln512_kernel(const float* __restrict__ X,
                  const float* __restrict__ gam, const float* __restrict__ bet,
                  __half* __restrict__ Y, float* __restrict__ res)
{
    long row = blockIdx.x;
    const int t = threadIdx.x;
    float4 v = reinterpret_cast<const float4*>(X + row * 512)[t];

    float s  = v.x + v.y + v.z + v.w;
    float sq = v.x * v.x + v.y * v.y + v.z * v.z + v.w * v.w;
#pragma unroll
    for (int o = 16; o > 0; o >>= 1) {
        s  += __shfl_xor_sync(0xffffffffu, s, o);
        sq += __shfl_xor_sync(0xffffffffu, sq, o);
    }
    __shared__ float sh_s[4], sh_q[4];
    int w = t >> 5, l = t & 31;
    if (l == 0) { sh_s[w] = s; sh_q[w] = sq; }
    __syncthreads();
    s  = sh_s[0] + sh_s[1] + sh_s[2] + sh_s[3];
    sq = sh_q[0] + sh_q[1] + sh_q[2] + sh_q[3];

    float mean = s * (1.f / 512.f);
    float var  = sq * (1.f / 512.f) - mean * mean;
    float rs   = rsqrtf(var + 1e-6f);

    if (res) reinterpret_cast<float4*>(res + row * 512)[t] = v;

    float4 g4 = reinterpret_cast<const float4*>(gam)[t];
    float4 b4 = reinterpret_cast<const float4*>(bet)[t];
    __half2* yo = reinterpret_cast<__half2*>(Y + row * 512) + 2 * t;
    yo[0] = __floats2half2_rn((v.x - mean) * rs * g4.x + b4.x,
                              (v.y - mean) * rs * g4.y + b4.y);
    yo[1] = __floats2half2_rn((v.z - mean) * rs * g4.z + b4.z,
                              (v.w - mean) * rs * g4.w + b4.w);
}

// ---------------------------------------------------------------------------
// Mask + softmax rows of 2048, in place (fp32, tf32-rounded output)
// + fp16 operand copy for the attn@V GEMM.
// ---------------------------------------------------------------------------
__global__ __launch_bounds__(256)
void softmax2048_kernel(float* __restrict__ Scores, const int* __restrict__ mask,
                        __half* __restrict__ Sh)
{
    long row = blockIdx.x;
    float* s      = Scores + row * 2048;
    const int* m  = mask   + row * 2048;
    __half* sh16  = Sh     + row * 2048;
    const int t = threadIdx.x;

    float vals[8];
    float mx = -1e30f;
#pragma unroll
    for (int i = 0; i < 8; i++) {
        int c = t + i * 256;
        float x = s[c];
        if (m[c] == 0) x = -1e9f;
        vals[i] = x;
        mx = fmaxf(mx, x);
    }
    __shared__ float sh[8];
#pragma unroll
    for (int o = 16; o > 0; o >>= 1) mx = fmaxf(mx, __shfl_xor_sync(0xffffffffu, mx, o));
    int w = t >> 5, l = t & 31;
    if (l == 0) sh[w] = mx;
    __syncthreads();
    mx = sh[0];
#pragma unroll
    for (int i = 1; i < 8; i++) mx = fmaxf(mx, sh[i]);
    __syncthreads();

    float sum = 0.f;
#pragma unroll
    for (int i = 0; i < 8; i++) {
        vals[i] = __expf(vals[i] - mx);
        sum += vals[i];
    }
#pragma unroll
    for (int o = 16; o > 0; o >>= 1) sum += __shfl_xor_sync(0xffffffffu, sum, o);
    if (l == 0) sh[w] = sum;
    __syncthreads();
    sum = sh[0] + sh[1] + sh[2] + sh[3] + sh[4] + sh[5] + sh[6] + sh[7];

    float inv = 1.f / sum;
#pragma unroll
    for (int i = 0; i < 8; i++) {
        int c = t + i * 256;
        float p = vals[i] * inv;
        s[c]    = roundtf(p);
        sh16[c] = __float2half_rn(p);
    }
}

// ---------------------------------------------------------------------------
// Launch.  Order puts the q-projection fp16 GEMM at launch index 3, where the
// R14 run showed ncu's capture actually lands.
// ---------------------------------------------------------------------------
extern "C" void kernel_launch(void* const* d_in, const int* in_sizes, int n_in,
                              void* d_out_, int out_size)
{
    const float* q    = (const float*)d_in[0];
    const float* k    = (const float*)d_in[1];
    const float* v    = (const float*)d_in[2];
    const int*   mask = (const int*)  d_in[3];
    const float* Wq   = (const float*)d_in[4];
    const float* bq   = (const float*)d_in[5];
    const float* Wk   = (const float*)d_in[6];
    const float* bk   = (const float*)d_in[7];
    const float* Wv   = (const float*)d_in[8];
    const float* bv   = (const float*)d_in[9];
    const float* gq   = (const float*)d_in[10];
    const float* beq  = (const float*)d_in[11];
    const float* gk   = (const float*)d_in[12];
    const float* bek  = (const float*)d_in[13];
    const float* gv   = (const float*)d_in[14];
    const float* bev  = (const float*)d_in[15];
    const float* W1   = (const float*)d_in[16];
    const float* b1   = (const float*)d_in[17];
    const float* W2   = (const float*)d_in[18];
    const float* b2   = (const float*)d_in[19];
    float* out = (float*)d_out_;

    float  *qp, *kp, *vp;
    __half *qh, *kh, *vh, *qn, *kn, *vn, *vpT, *ath, *wqT, *wkT, *wvT, *w1T, *w2T;
    cudaGetSymbolAddress((void**)&qp,  g_qp);
    cudaGetSymbolAddress((void**)&kp,  g_kp);
    cudaGetSymbolAddress((void**)&vp,  g_vp);
    cudaGetSymbolAddress((void**)&qh,  g_qh);
    cudaGetSymbolAddress((void**)&kh,  g_kh);
    cudaGetSymbolAddress((void**)&vh,  g_vh);
    cudaGetSymbolAddress((void**)&qn,  g_qn);
    cudaGetSymbolAddress((void**)&kn,  g_kn);
    cudaGetSymbolAddress((void**)&vn,  g_vn);
    cudaGetSymbolAddress((void**)&vpT, g_vpT);
    cudaGetSymbolAddress((void**)&ath, g_ath);
    cudaGetSymbolAddress((void**)&wqT, g_wqT);
    cudaGetSymbolAddress((void**)&wkT, g_wkT);
    cudaGetSymbolAddress((void**)&wvT, g_wvT);
    cudaGetSymbolAddress((void**)&w1T, g_w1T);
    cudaGetSymbolAddress((void**)&w2T, g_w2T);
    __half* t1h = qn;   // qn dead after scores GEMM
    __half* t2h = kn;   // kn dead after scores GEMM

    cudaFuncSetAttribute(mma_gemm<true,  false, false>, cudaFuncAttributeMaxDynamicSharedMemorySize, SMEM_DYN);
    cudaFuncSetAttribute(mma_gemm<false, false, false>, cudaFuncAttributeMaxDynamicSharedMemorySize, SMEM_DYN);
    cudaFuncSetAttribute(mma_gemm<false, false, true >, cudaFuncAttributeMaxDynamicSharedMemorySize, SMEM_DYN);
    cudaFuncSetAttribute(mma_gemm<true,  true,  true >, cudaFuncAttributeMaxDynamicSharedMemorySize, SMEM_DYN);

    dim3 tb(32, 8);
    dim3 blk(128);
    const long NQKV = (long)NTc * DMc;
    const int  CVB  = (int)(NQKV / (256 * 8));

    // #0-#2: prerequisites for q-projection only
    cvt_f2h<<<CVB, 256>>>(q, qh, NQKV);                                // #0
    transpose_f2h<<<dim3(DKc/32, DMc/32), tb>>>(Wq, wqT, DMc, DKc);    // #1
    cvt_f2h<<<CVB, 256>>>(k, kh, NQKV);                                // #2

    // #3: q projection (+bias) -> fp32 qp            <- ncu capture slot
    mma_gemm<true, false, false><<<dim3(DKc/BN, NTc/BM, 1), blk, SMEM_DYN>>>(
        qh, wqT, bq, qp, NTc, DKc, DMc, DMc, 0, 0, 0, 1.f);            // #3

    // remaining prerequisites + k,v projections
    transpose_f2h<<<dim3(DKc/32, DMc/32), tb>>>(Wk, wkT, DMc, DKc);
    cvt_f2h<<<CVB, 256>>>(v, vh, NQKV);
    transpose_f2h<<<dim3(DVc/32, DMc/32), tb>>>(Wv, wvT, DMc, DVc);
    mma_gemm<true, false, false><<<dim3(DKc/BN, NTc/BM, 1), blk, SMEM_DYN>>>(
        kh, wkT, bk, kp, NTc, DKc, DMc, DMc, 0, 0, 0, 1.f);
    mma_gemm<true, false, false><<<dim3(DVc/BN, NTc/BM, 1), blk, SMEM_DYN>>>(
        vh, wvT, bv, vp, NTc, DVc, DMc, DMc, 0, 0, 0, 1.f);

    // LayerNorm: fp32 in -> fp16 normalized out; q-LN also emits raw residual.
    ln512_kernel<<<NTc, 128>>>(qp, gq, beq, qn, out + OFF_RES);
    ln512_kernel<<<NTc, 128>>>(kp, gk, bek, kn, nullptr);
    ln512_kernel<<<NTc, 128>>>(vp, gv, bev, vn, nullptr);

    // vn^T (fp16) for the attn@V B-operand
    transpose_h2h<<<dim3(DVc/32, NTc/32), tb>>>(vn, vpT, NTc, DVc);

    // scores = (qn @ kn^T) / sqrt(dk) -> fp32 attn region
    mma_gemm<false, false, false><<<dim3(Sc/BN, Sc/BM, Bc), blk, SMEM_DYN>>>(
        qn, kn, nullptr, out + OFF_ATT, Sc, Sc, DKc, DKc,
        (long)Sc * DKc, (long)Sc * DKc, (long)Sc * Sc, INV_TEMP);

    // mask + softmax (tf32-rounded fp32 output, fp16 operand copy)
    softmax2048_kernel<<<NTc, 256>>>(out + OFF_ATT, mask, ath);

    // MLP weight transposes (fp32 -> fp16)
    transpose_f2h<<<dim3(DVc/32,  DVc/32), tb>>>(W1, w1T, DVc, DVc);
    transpose_f2h<<<dim3(DOUTc/32, DVc/32), tb>>>(W2, w2T, DVc, DOUTc);

    // out1 = attn @ vn -> fp16 t1h
    mma_gemm<false, false, true><<<dim3(DVc/BN, Sc/BM, Bc), blk, SMEM_DYN>>>(
        ath, vpT, nullptr, t1h, Sc, DVc, Sc, NTc,
        (long)Sc * Sc, (long)Sc, (long)Sc * DVc, 1.f);

    // h = relu(out1 @ W1 + b1) -> fp16 t2h
    mma_gemm<true, true, true><<<dim3(DVc/BN, NTc/BM, 1), blk, SMEM_DYN>>>(
        t1h, w1T, b1, t2h, NTc, DVc, DVc, DVc, 0, 0, 0, 1.f);

    // out = h @ W2 + b2 -> fp32 d_out
    mma_gemm<true, false, false><<<dim3(DOUTc/BN, NTc/BM, 1), blk, SMEM_DYN>>>(
        t2h, w2T, b2, out + OFF_OUT, NTc, DOUTc, DVc, DVc, 0, 0, 0, 1.f);
}

// round 16
// speedup vs baseline: 1.0509x; 1.0509x over previous
#include <cuda_runtime.h>
#include <cuda_fp16.h>
#include <math.h>
#include <stdint.h>

// ---------------------------------------------------------------------------
// Problem constants
// ---------------------------------------------------------------------------
#define Bc    8
#define Sc    2048
#define DMc   1024
#define DKc   512
#define DVc   512
#define DOUTc 1024
#define NTc   (Bc * Sc)              // 16384 tokens

static const long OFF_OUT = 0L;
static const long OFF_RES = (long)NTc * DOUTc;                   // 16777216
static const long OFF_ATT = OFF_RES + (long)NTc * DKc;           // 25165824

#define INV_TEMP 0.04419417382415922f   // 1/sqrt(512)

// ---------------------------------------------------------------------------
// Scratch (static device globals — no allocation at runtime)
// Stacked [3] arrays allow the QKV pipeline to run as ONE batched GEMM.
// ---------------------------------------------------------------------------
__device__ __align__(16) __half g_qkvh[(size_t)3 * NTc * DMc];  // fp16(q,k,v)
__device__ __align__(16) __half g_wT3 [(size_t)3 * DKc * DMc];  // Wq^T,Wk^T,Wv^T fp16
__device__ __align__(16) float  g_b3  [3 * DKc];                // bq,bk,bv stacked
__device__ __align__(16) float  g_qkvp[(size_t)3 * NTc * DKc];  // fp32 proj outputs
__device__ __align__(16) __half g_nh  [(size_t)3 * NTc * DKc];  // LN(q),LN(k),LN(v) fp16
__device__ __align__(16) __half g_vpT [(size_t)DVc * NTc];      // LN(v)^T
__device__ __align__(16) __half g_ath [(size_t)NTc * Sc];       // fp16(attn)
__device__ __align__(16) __half g_w1T [(size_t)DVc * DVc];
__device__ __align__(16) __half g_w2T [(size_t)DOUTc * DVc];

// ---------------------------------------------------------------------------
// helpers
// ---------------------------------------------------------------------------
__device__ __forceinline__ uint32_t f2tf32(float f) {
    uint32_t r;
    asm("cvt.rna.tf32.f32 %0, %1;" : "=r"(r) : "f"(f));
    return r;
}
__device__ __forceinline__ float roundtf(float f) { return __uint_as_float(f2tf32(f)); }

__device__ __forceinline__ uint32_t smem_u32(const void* p) {
    uint32_t a;
    asm("{ .reg .u64 t; cvta.to.shared.u64 t, %1; cvt.u32.u64 %0, t; }" : "=r"(a) : "l"(p));
    return a;
}
__device__ __forceinline__ void cp_async16(uint32_t dst, const void* src) {
    asm volatile("cp.async.cg.shared.global [%0], [%1], 16;" :: "r"(dst), "l"(src));
}
#define CP_COMMIT() asm volatile("cp.async.commit_group;" ::: "memory")
#define CP_WAIT1()  asm volatile("cp.async.wait_group 1;" ::: "memory")

__device__ __forceinline__ void ldsm_x4(uint32_t* r, uint32_t addr) {
    asm volatile("ldmatrix.sync.aligned.m8n8.x4.shared.b16 {%0,%1,%2,%3}, [%4];"
                 : "=r"(r[0]), "=r"(r[1]), "=r"(r[2]), "=r"(r[3]) : "r"(addr));
}
// fp16 mma, fp32 accumulate
__device__ __forceinline__ void mma_16x8x16(float* c, const uint32_t* a, const uint32_t* b) {
    asm volatile(
        "mma.sync.aligned.m16n8k16.row.col.f32.f16.f16.f32 "
        "{%0,%1,%2,%3}, {%4,%5,%6,%7}, {%8,%9}, {%0,%1,%2,%3};"
        : "+f"(c[0]), "+f"(c[1]), "+f"(c[2]), "+f"(c[3])
        : "r"(a[0]), "r"(a[1]), "r"(a[2]), "r"(a[3]), "r"(b[0]), "r"(b[1]));
}

// ---------------------------------------------------------------------------
// fp16 GEMM: C[M,N] = alpha * A[M,K] @ Bt[N,K]^T (+bias) (+relu)
// BM=BN=128, BK=32, 128 threads (4 warps, 64x64 warp tiles), 3-stage cp.async
// (wait_group 1) — R14's measured-best config. Stride 40 halfs: conflict-free.
// Batched via grid.z with sA/sB/sC/sBias strides.
// ---------------------------------------------------------------------------
#define STRIDE_H 40
#define TILE_BYTES_H (128 * STRIDE_H * 2)     // 10240
#define NSTAGE 3
#define SMEM_DYN (NSTAGE * 2 * TILE_BYTES_H)  // 61440

#define BM 128
#define BN 128
#define BK 32

template<bool BIAS, bool RELU, bool OUT_HALF>
__global__ __launch_bounds__(128, 2)
void mma_gemm(const __half* __restrict__ A, const __half* __restrict__ Bt,
              const float* __restrict__ bias, void* __restrict__ Cv,
              int M, int N, int K, int ldB,
              long sA, long sB, long sC, long sBias, float alpha)
{
    extern __shared__ __align__(16) __half smem[];

    A    += (long)blockIdx.z * sA;
    Bt   += (long)blockIdx.z * sB;
    if (BIAS) bias += (long)blockIdx.z * sBias;

    const int tid  = threadIdx.x;
    const int wid  = tid >> 5;
    const int lane = tid & 31;
    const int g    = lane >> 2;
    const int tg   = lane & 3;
    const int wm   = (wid & 1);
    const int wn   = (wid >> 1);
    const int m0   = blockIdx.y * BM;
    const int n0   = blockIdx.x * BN;

    const uint32_t sAu = smem_u32(smem);
    const uint32_t sBu = sAu + NSTAGE * TILE_BYTES_H;

    int rowc[4];
#pragma unroll
    for (int i = 0; i < 4; i++) rowc[i] = (i * 128 + tid) >> 2;
    const int koct = (tid & 3) * 8;

    const int grp = lane >> 3;
    const uint32_t aAddr0 = sAu + (uint32_t)((((wm * 64 + (grp & 1) * 8 + (lane & 7)) * STRIDE_H)
                                              + (grp >> 1) * 8) * 2);
    const uint32_t bAddr0 = sBu + (uint32_t)((((wn * 64 + (grp >> 1) * 8 + (lane & 7)) * STRIDE_H)
                                              + (grp & 1) * 8) * 2);

    float acc[4][8][4];
#pragma unroll
    for (int i = 0; i < 4; i++)
#pragma unroll
        for (int j = 0; j < 8; j++)
#pragma unroll
            for (int r = 0; r < 4; r++) acc[i][j][r] = 0.f;

    const int T = K / BK;

    // ---- prologue: stages 0,1
#pragma unroll
    for (int s = 0; s < 2; s++) {
        if (s < T) {
            const int kc = s * BK;
            const uint32_t so = (uint32_t)(s * TILE_BYTES_H);
#pragma unroll
            for (int i = 0; i < 4; i++) {
                uint32_t d = so + (uint32_t)((rowc[i] * STRIDE_H + koct) * 2);
                cp_async16(sAu + d, A  + (long)(m0 + rowc[i]) * K   + kc + koct);
                cp_async16(sBu + d, Bt + (long)(n0 + rowc[i]) * ldB + kc + koct);
            }
        }
        CP_COMMIT();
    }

    int cur = 0;
    for (int it = 0; it < T; it++) {
        CP_WAIT1();
        __syncthreads();

        if (it + 2 < T) {
            int ib = cur + 2; if (ib >= NSTAGE) ib -= NSTAGE;
            const int kc = (it + 2) * BK;
            const uint32_t so = (uint32_t)(ib * TILE_BYTES_H);
#pragma unroll
            for (int i = 0; i < 4; i++) {
                uint32_t d = so + (uint32_t)((rowc[i] * STRIDE_H + koct) * 2);
                cp_async16(sAu + d, A  + (long)(m0 + rowc[i]) * K   + kc + koct);
                cp_async16(sBu + d, Bt + (long)(n0 + rowc[i]) * ldB + kc + koct);
            }
        }
        CP_COMMIT();

        const uint32_t bufOff = (uint32_t)(cur * TILE_BYTES_H);
#pragma unroll
        for (int kt = 0; kt < 2; kt++) {
            const uint32_t kOff = bufOff + kt * 32;
            uint32_t a[4][4];
#pragma unroll
            for (int mi = 0; mi < 4; mi++)
                ldsm_x4(a[mi], aAddr0 + kOff + mi * (16 * STRIDE_H * 2));
            uint32_t b[4][4];
#pragma unroll
            for (int p = 0; p < 4; p++)
                ldsm_x4(b[p], bAddr0 + kOff + p * (16 * STRIDE_H * 2));
#pragma unroll
            for (int mi = 0; mi < 4; mi++)
#pragma unroll
                for (int ni = 0; ni < 8; ni++)
                    mma_16x8x16(acc[mi][ni], a[mi], &b[ni >> 1][(ni & 1) * 2]);
        }

        if (++cur == NSTAGE) cur = 0;
    }

    // ---- epilogue
#pragma unroll
    for (int mi = 0; mi < 4; mi++) {
#pragma unroll
        for (int half = 0; half < 2; half++) {
            const long row = m0 + wm * 64 + mi * 16 + g + half * 8;
#pragma unroll
            for (int ni = 0; ni < 8; ni++) {
                const int col = n0 + wn * 64 + ni * 8 + 2 * tg;
                float rx = acc[mi][ni][half * 2 + 0] * alpha;
                float ry = acc[mi][ni][half * 2 + 1] * alpha;
                if (BIAS) {
                    float2 b2v = *reinterpret_cast<const float2*>(bias + col);
                    rx += b2v.x; ry += b2v.y;
                }
                if (RELU) { rx = fmaxf(rx, 0.f); ry = fmaxf(ry, 0.f); }
                if (OUT_HALF) {
                    __half* C16 = (__half*)Cv + (long)blockIdx.z * sC;
                    *reinterpret_cast<__half2*>(C16 + row * (long)N + col) =
                        __floats2half2_rn(rx, ry);
                } else {
                    float* C = (float*)Cv + (long)blockIdx.z * sC;
                    float2 r; r.x = rx; r.y = ry;
                    *reinterpret_cast<float2*>(C + row * (long)N + col) = r;
                }
            }
        }
    }
}

// ---------------------------------------------------------------------------
// Merged q/k/v fp32->fp16 convert (grid.y selects source) + bias concat
// ---------------------------------------------------------------------------
__global__ __launch_bounds__(256)
void cvt_qkv(const float* __restrict__ q, const float* __restrict__ k,
             const float* __restrict__ v, __half* __restrict__ out,
             const float* __restrict__ bq, const float* __restrict__ bk,
             const float* __restrict__ bv, float* __restrict__ b3, long n)
{
    if (blockIdx.x == 0 && blockIdx.y == 0) {
        for (int j = threadIdx.x; j < DKc; j += 256) {
            b3[j]            = bq[j];
            b3[DKc + j]      = bk[j];
            b3[2 * DKc + j]  = bv[j];
        }
    }
    const float* src = (blockIdx.y == 0) ? q : (blockIdx.y == 1) ? k : v;
    __half* dst = out + (long)blockIdx.y * n;
    long i = ((long)blockIdx.x * 256 + threadIdx.x) * 8;
    if (i >= n) return;
    float4 a = *reinterpret_cast<const float4*>(src + i);
    float4 b = *reinterpret_cast<const float4*>(src + i + 4);
    __half2* o = reinterpret_cast<__half2*>(dst + i);
    o[0] = __floats2half2_rn(a.x, a.y);
    o[1] = __floats2half2_rn(a.z, a.w);
    o[2] = __floats2half2_rn(b.x, b.y);
    o[3] = __floats2half2_rn(b.z, b.w);
}

// ---------------------------------------------------------------------------
// Merged QKV weight transpose: z selects Wq/Wk/Wv (all [DMc, DKc] fp32)
// ---------------------------------------------------------------------------
__global__ __launch_bounds__(256)
void transposeW3(const float* __restrict__ Wq, const float* __restrict__ Wk,
                 const float* __restrict__ Wv, __half* __restrict__ out3)
{
    const float* in = (blockIdx.z == 0) ? Wq : (blockIdx.z == 1) ? Wk : Wv;
    __half* out = out3 + (size_t)blockIdx.z * DKc * DMc;
    __shared__ float t[32][33];
    int c0 = blockIdx.x * 32, r0 = blockIdx.y * 32;
#pragma unroll
    for (int i = 0; i < 32; i += 8)
        t[threadIdx.y + i][threadIdx.x] = in[(long)(r0 + threadIdx.y + i) * DKc + c0 + threadIdx.x];
    __syncthreads();
#pragma unroll
    for (int i = 0; i < 32; i += 8)
        out[(long)(c0 + threadIdx.y + i) * DMc + r0 + threadIdx.x] =
            __float2half_rn(t[threadIdx.x][threadIdx.y + i]);
}

// ---------------------------------------------------------------------------
// 32x32 transposes: fp32->fp16 (single weight), fp16->fp16 (vn)
// ---------------------------------------------------------------------------
__global__ __launch_bounds__(256)
void transpose_f2h(const float* __restrict__ in, __half* __restrict__ out, int R, int C)
{
    __shared__ float t[32][33];
    int c0 = blockIdx.x * 32, r0 = blockIdx.y * 32;
#pragma unroll
    for (int i = 0; i < 32; i += 8)
        t[threadIdx.y + i][threadIdx.x] = in[(long)(r0 + threadIdx.y + i) * C + c0 + threadIdx.x];
    __syncthreads();
#pragma unroll
    for (int i = 0; i < 32; i += 8)
        out[(long)(c0 + threadIdx.y + i) * R + r0 + threadIdx.x] =
            __float2half_rn(t[threadIdx.x][threadIdx.y + i]);
}

__global__ __launch_bounds__(256)
void transpose_h2h(const __half* __restrict__ in, __half* __restrict__ out, int R, int C)
{
    __shared__ float t[32][33];
    int c0 = blockIdx.x * 32, r0 = blockIdx.y * 32;
#pragma unroll
    for (int i = 0; i < 32; i += 8)
        t[threadIdx.y + i][threadIdx.x] =
            __half2float(in[(long)(r0 + threadIdx.y + i) * C + c0 + threadIdx.x]);
    __syncthreads();
#pragma unroll
    for (int i = 0; i < 32; i += 8)
        out[(long)(c0 + threadIdx.y + i) * R + r0 + threadIdx.x] =
            __float2half_rn(t[threadIdx.x][threadIdx.y + i]);
}

// ---------------------------------------------------------------------------
// Merged LayerNorm D=512 over stacked [3][NTc,512]: grid.y selects q/k/v.
// fp16 normalized out; y==0 also emits raw fp32 residual.
// ---------------------------------------------------------------------------
__global__ __launch_bounds__(128)
void ln512_merged(const float* __restrict__ Xb,
                  const float* __restrict__ g0, const float* __restrict__ be0,
                  const float* __restrict__ g1, const float* __restrict__ be1,
                  const float* __restrict__ g2, const float* __restrict__ be2,
                  __half* __restrict__ Yb, float* __restrict__ res)
{
    const int which = blockIdx.y;
    const float* gam = (which == 0) ? g0 : (which == 1) ? g1 : g2;
    const float* bet = (which == 0) ? be0 : (which == 1) ? be1 : be2;
    const float* X = Xb + (size_t)which * NTc * 512;
    __half* Y      = Yb + (size_t)which * NTc * 512;

    long row = blockIdx.x;
    const int t = threadIdx.x;
    float4 v = reinterpret_cast<const float4*>(X + row * 512)[t];

    float s  = v.x + v.y + v.z + v.w;
    float sq = v.x * v.x + v.y * v.y + v.z * v.z + v.w * v.w;
#pragma unroll
    for (int o = 16; o > 0; o >>= 1) {
        s  += __shfl_xor_sync(0xffffffffu, s, o);
        sq += __shfl_xor_sync(0xffffffffu, sq, o);
    }
    __shared__ float sh_s[4], sh_q[4];
    int w = t >> 5, l = t & 31;
    if (l == 0) { sh_s[w] = s; sh_q[w] = sq; }
    __syncthreads();
    s  = sh_s[0] + sh_s[1] + sh_s[2] + sh_s[3];
    sq = sh_q[0] + sh_q[1] + sh_q[2] + sh_q[3];

    float mean = s * (1.f / 512.f);
    float var  = sq * (1.f / 512.f) - mean * mean;
    float rs   = rsqrtf(var + 1e-6f);

    if (which == 0) reinterpret_cast<float4*>(res + row * 512)[t] = v;

    float4 g4 = reinterpret_cast<const float4*>(gam)[t];
    float4 b4 = reinterpret_cast<const float4*>(bet)[t];
    __half2* yo = reinterpret_cast<__half2*>(Y + row * 512) + 2 * t;
    yo[0] = __floats2half2_rn((v.x - mean) * rs * g4.x + b4.x,
                              (v.y - mean) * rs * g4.y + b4.y);
    yo[1] = __floats2half2_rn((v.z - mean) * rs * g4.z + b4.z,
                              (v.w - mean) * rs * g4.w + b4.w);
}

// ---------------------------------------------------------------------------
// Mask + softmax rows of 2048, in place (fp32, tf32-rounded) + fp16 copy.
// ---------------------------------------------------------------------------
__global__ __launch_bounds__(256)
void softmax2048_kernel(float* __restrict__ Scores, const int* __restrict__ mask,
                        __half* __restrict__ Sh)
{
    long row = blockIdx.x;
    float* s      = Scores + row * 2048;
    const int* m  = mask   + row * 2048;
    __half* sh16  = Sh     + row * 2048;
    const int t = threadIdx.x;

    float vals[8];
    float mx = -1e30f;
#pragma unroll
    for (int i = 0; i < 8; i++) {
        int c = t + i * 256;
        float x = s[c];
        if (m[c] == 0) x = -1e9f;
        vals[i] = x;
        mx = fmaxf(mx, x);
    }
    __shared__ float sh[8];
#pragma unroll
    for (int o = 16; o > 0; o >>= 1) mx = fmaxf(mx, __shfl_xor_sync(0xffffffffu, mx, o));
    int w = t >> 5, l = t & 31;
    if (l == 0) sh[w] = mx;
    __syncthreads();
    mx = sh[0];
#pragma unroll
    for (int i = 1; i < 8; i++) mx = fmaxf(mx, sh[i]);
    __syncthreads();

    float sum = 0.f;
#pragma unroll
    for (int i = 0; i < 8; i++) {
        vals[i] = __expf(vals[i] - mx);
        sum += vals[i];
    }
#pragma unroll
    for (int o = 16; o > 0; o >>= 1) sum += __shfl_xor_sync(0xffffffffu, sum, o);
    if (l == 0) sh[w] = sum;
    __syncthreads();
    sum = sh[0] + sh[1] + sh[2] + sh[3] + sh[4] + sh[5] + sh[6] + sh[7];

    float inv = 1.f / sum;
#pragma unroll
    for (int i = 0; i < 8; i++) {
        int c = t + i * 256;
        float p = vals[i] * inv;
        s[c]    = roundtf(p);
        sh16[c] = __float2half_rn(p);
    }
}

// ---------------------------------------------------------------------------
// Launch.  Index 3 (ncu capture slot) = batched QKV GEMM.
// ---------------------------------------------------------------------------
extern "C" void kernel_launch(void* const* d_in, const int* in_sizes, int n_in,
                              void* d_out_, int out_size)
{
    const float* q    = (const float*)d_in[0];
    const float* k    = (const float*)d_in[1];
    const float* v    = (const float*)d_in[2];
    const int*   mask = (const int*)  d_in[3];
    const float* Wq   = (const float*)d_in[4];
    const float* bq   = (const float*)d_in[5];
    const float* Wk   = (const float*)d_in[6];
    const float* bk   = (const float*)d_in[7];
    const float* Wv   = (const float*)d_in[8];
    const float* bv   = (const float*)d_in[9];
    const float* gq   = (const float*)d_in[10];
    const float* beq  = (const float*)d_in[11];
    const float* gk   = (const float*)d_in[12];
    const float* bek  = (const float*)d_in[13];
    const float* gv   = (const float*)d_in[14];
    const float* bev  = (const float*)d_in[15];
    const float* W1   = (const float*)d_in[16];
    const float* b1   = (const float*)d_in[17];
    const float* W2   = (const float*)d_in[18];
    const float* b2   = (const float*)d_in[19];
    float* out = (float*)d_out_;

    __half *qkvh, *wT3, *nh, *vpT, *ath, *w1T, *w2T;
    float  *b3, *qkvp;
    cudaGetSymbolAddress((void**)&qkvh, g_qkvh);
    cudaGetSymbolAddress((void**)&wT3,  g_wT3);
    cudaGetSymbolAddress((void**)&b3,   g_b3);
    cudaGetSymbolAddress((void**)&qkvp, g_qkvp);
    cudaGetSymbolAddress((void**)&nh,   g_nh);
    cudaGetSymbolAddress((void**)&vpT,  g_vpT);
    cudaGetSymbolAddress((void**)&ath,  g_ath);
    cudaGetSymbolAddress((void**)&w1T,  g_w1T);
    cudaGetSymbolAddress((void**)&w2T,  g_w2T);

    __half* qn = nh;                               // LN(q)
    __half* kn = nh + (size_t)NTc * DKc;           // LN(k)
    __half* vn = nh + (size_t)2 * NTc * DKc;       // LN(v)
    __half* t1h = qn;   // qn dead after scores GEMM
    __half* t2h = kn;   // kn dead after scores GEMM

    cudaFuncSetAttribute(mma_gemm<true,  false, false>, cudaFuncAttributeMaxDynamicSharedMemorySize, SMEM_DYN);
    cudaFuncSetAttribute(mma_gemm<false, false, false>, cudaFuncAttributeMaxDynamicSharedMemorySize, SMEM_DYN);
    cudaFuncSetAttribute(mma_gemm<false, false, true >, cudaFuncAttributeMaxDynamicSharedMemorySize, SMEM_DYN);
    cudaFuncSetAttribute(mma_gemm<true,  true,  true >, cudaFuncAttributeMaxDynamicSharedMemorySize, SMEM_DYN);

    dim3 tb(32, 8);
    dim3 blk(128);
    const long NQKV = (long)NTc * DMc;
    const int  CVB  = (int)(NQKV / (256 * 8));

    // #0: merged q/k/v convert + bias concat
    cvt_qkv<<<dim3(CVB, 3), 256>>>(q, k, v, qkvh, bq, bk, bv, b3, NQKV);
    // #1: merged QKV weight transposes
    transposeW3<<<dim3(DKc/32, DMc/32, 3), tb>>>(Wq, Wk, Wv, wT3);
    // #2: W1 transpose (independent; fills the pre-capture slot)
    transpose_f2h<<<dim3(DVc/32, DVc/32), tb>>>(W1, w1T, DVc, DVc);

    // #3: batched QKV projection (+per-z bias) -> fp32 qkvp   <- ncu capture
    mma_gemm<true, false, false><<<dim3(DKc/BN, NTc/BM, 3), blk, SMEM_DYN>>>(
        qkvh, wT3, b3, qkvp, NTc, DKc, DMc, DMc,
        (long)NTc * DMc, (long)DKc * DMc, (long)NTc * DKc, DKc, 1.f);

    // merged LayerNorm (q-slice also emits raw residual)
    ln512_merged<<<dim3(NTc, 3), 128>>>(qkvp, gq, beq, gk, bek, gv, bev,
                                        nh, out + OFF_RES);

    // vn^T (fp16) for the attn@V B-operand
    transpose_h2h<<<dim3(DVc/32, NTc/32), tb>>>(vn, vpT, NTc, DVc);

    // scores = (qn @ kn^T) / sqrt(dk) -> fp32 attn region
    mma_gemm<false, false, false><<<dim3(Sc/BN, Sc/BM, Bc), blk, SMEM_DYN>>>(
        qn, kn, nullptr, out + OFF_ATT, Sc, Sc, DKc, DKc,
        (long)Sc * DKc, (long)Sc * DKc, (long)Sc * Sc, 0, INV_TEMP);

    // mask + softmax (tf32-rounded fp32 output, fp16 operand copy)
    softmax2048_kernel<<<NTc, 256>>>(out + OFF_ATT, mask, ath);

    // W2 transpose
    transpose_f2h<<<dim3(DOUTc/32, DVc/32), tb>>>(W2, w2T, DVc, DOUTc);

    // out1 = attn @ vn -> fp16 t1h
    mma_gemm<false, false, true><<<dim3(DVc/BN, Sc/BM, Bc), blk, SMEM_DYN>>>(
        ath, vpT, nullptr, t1h, Sc, DVc, Sc, NTc,
        (long)Sc * Sc, (long)Sc, (long)Sc * DVc, 0, 1.f);

    // h = relu(out1 @ W1 + b1) -> fp16 t2h
    mma_gemm<true, true, true><<<dim3(DVc/BN, NTc/BM, 1), blk, SMEM_DYN>>>(
        t1h, w1T, b1, t2h, NTc, DVc, DVc, DVc, 0, 0, 0, 0, 1.f);

    // out = h @ W2 + b2 -> fp32 d_out
    mma_gemm<true, false, false><<<dim3(DOUTc/BN, NTc/BM, 1), blk, SMEM_DYN>>>(
        t2h, w2T, b2, out + OFF_OUT, NTc, DOUTc, DVc, DVc, 0, 0, 0, 0, 1.f);
}